// round 11
// baseline (speedup 1.0000x reference)
#include <cuda_runtime.h>
#include <cuda_bf16.h>
#include <stdint.h>

#define LF     4095
#define LFP    4096
#define NCH    256
#define NB     4
#define SEQLEN 32768
#define EPSF   1e-5f
#define TILE_INT 26

// ---------------- scratch (static device globals; no allocation) ----------------
__device__ float g_enc [NB*NCH*LFP];
__device__ float g_x   [NB*NCH*LFP];
__device__ float g_m1  [NB*NCH*LFP];
__device__ float g_msk [NB*NCH*LFP];
__device__ __nv_bfloat16 g_xnh[NB*NCH*LFP];
__device__ __nv_bfloat16 g_xnl[NB*NCH*LFP];
__device__ __nv_bfloat16 g_x3h[NB*NCH*LFP];
__device__ __nv_bfloat16 g_x3l[NB*NCH*LFP];
__device__ float g_wc  [12*3*NCH];
__device__ float g_bcol[12*3];
__device__ __nv_bfloat16 g_wh[6*NCH*NCH];
__device__ __nv_bfloat16 g_wl[6*NCH*NCH];

__device__ __forceinline__ void split1(float x, __nv_bfloat16& h, __nv_bfloat16& l)
{
    h = __float2bfloat16(x);
    l = __float2bfloat16(x - __bfloat162float(h));
}

// ---------------- fused: collapse w2@w1 + split 6 GEMM weight matrices ----------
__global__ void k_prepsplit(const float* __restrict__ w1, const float* __restrict__ b1,
                            const float* __restrict__ w2, const float* __restrict__ b2,
                            const float* __restrict__ mi, const float* __restrict__ sk,
                            const float* __restrict__ mf)
{
    int y = blockIdx.y;
    if (y < 6) {
        int idx = blockIdx.x*256 + threadIdx.x;
        const float* src = (y == 0) ? mi : (y <= 4 ? sk + (size_t)(y-1)*NCH*NCH : mf);
        float v = src[idx];
        __nv_bfloat16 h, l; split1(v, h, l);
        g_wh[(size_t)y*NCH*NCH + idx] = h;
        g_wl[(size_t)y*NCH*NCH + idx] = l;
    } else if (blockIdx.x < 36) {
        int bp = blockIdx.x / 3, j = blockIdx.x % 3;
        int c = threadIdx.x;
        const float* w1p = w1 + (size_t)bp*64*NCH;
        const float* w2p = w2 + ((size_t)bp*3 + j)*64;
        float acc = 0.f;
        #pragma unroll 8
        for (int cr = 0; cr < 64; cr++) acc += w2p[cr] * w1p[(size_t)cr*NCH + c];
        g_wc[((size_t)bp*3 + j)*NCH + c] = acc;
        if (c == 0) {
            const float* b1p = b1 + bp*64;
            float bb = b2[bp*3 + j];
            for (int cr = 0; cr < 64; cr++) bb += w2p[cr]*b1p[cr];
            g_bcol[bp*3 + j] = bb;
        }
    }
}

// ---------------- encoder + fused channel-LN ----------------
__global__ void k_enc_ln(const float* __restrict__ ac, const float* __restrict__ bc,
                         const float* __restrict__ acw, const float* __restrict__ bcw,
                         const float* __restrict__ lng, const float* __restrict__ lnb,
                         float* __restrict__ enc,
                         __nv_bfloat16* __restrict__ xnh, __nv_bfloat16* __restrict__ xnl)
{
    int b  = blockIdx.y;
    int t0 = blockIdx.x * 32;
    int tx = threadIdx.x, ty = threadIdx.y;
    __shared__ float sa[264], sb[264];
    __shared__ float ss[8][33], sq[8][33];
    int tid  = ty*32 + tx;
    int base = t0 * 8;
    for (int i = tid; i < 264; i += 256) {
        int gi = base + i;
        sa[i] = (gi < SEQLEN) ? ac[(size_t)b*SEQLEN + gi] : 0.f;
        sb[i] = (gi < SEQLEN) ? bc[(size_t)b*SEQLEN + gi] : 0.f;
    }
    __syncthreads();
    int t = t0 + tx;
    bool valid = (t < LF);
    const size_t bbase = (size_t)b*NCH*LFP;
    float vals[32];
    float s = 0.f, q = 0.f;
    #pragma unroll
    for (int i = 0; i < 32; i++) {
        int n = ty + i*8;
        float acc = 0.f;
        #pragma unroll
        for (int l = 0; l < 16; l++)
            acc += sa[tx*8 + l]*acw[n*16 + l] + sb[tx*8 + l]*bcw[n*16 + l];
        if (!valid) acc = 0.f;
        vals[i] = acc; s += acc; q += acc*acc;
        enc[bbase + (size_t)n*LFP + t] = acc;
    }
    ss[ty][tx] = s; sq[ty][tx] = q;
    __syncthreads();
    if (ty == 0) {
        float S = 0.f, Q = 0.f;
        #pragma unroll
        for (int j = 0; j < 8; j++) { S += ss[j][tx]; Q += sq[j][tx]; }
        float mu  = S * (1.f/NCH);
        float var = Q * (1.f/NCH) - mu*mu;
        ss[0][tx] = mu;
        sq[0][tx] = rsqrtf(var + EPSF);
    }
    __syncthreads();
    float mu = ss[0][tx], rs = sq[0][tx];
    #pragma unroll
    for (int i = 0; i < 32; i++) {
        int c = ty + i*8;
        float v = valid ? (vals[i] - mu)*rs*lng[c] + lnb[c] : 0.f;
        __nv_bfloat16 h, l; split1(v, h, l);
        size_t gi = bbase + (size_t)c*LFP + t;
        xnh[gi] = h; xnl[gi] = l;
    }
}

// ---------------- tensor-core pointwise GEMM (batched-LDSM per ktile) ----------
#define LDSM4(R, addr)  asm volatile("ldmatrix.sync.aligned.m8n8.x4.shared.b16 {%0,%1,%2,%3}, [%4];" \
    : "=r"(R[0]),"=r"(R[1]),"=r"(R[2]),"=r"(R[3]) : "r"(addr))
#define LDSM4T(R, addr) asm volatile("ldmatrix.sync.aligned.m8n8.x4.trans.shared.b16 {%0,%1,%2,%3}, [%4];" \
    : "=r"(R[0]),"=r"(R[1]),"=r"(R[2]),"=r"(R[3]) : "r"(addr))
#define MMA_BF16(D, A, B0, B1) asm volatile( \
    "mma.sync.aligned.m16n8k16.row.col.f32.bf16.bf16.f32 " \
    "{%0,%1,%2,%3}, {%4,%5,%6,%7}, {%8,%9}, {%0,%1,%2,%3};" \
    : "+f"(D[0]), "+f"(D[1]), "+f"(D[2]), "+f"(D[3]) \
    : "r"(A[0]), "r"(A[1]), "r"(A[2]), "r"(A[3]), "r"(B0), "r"(B1))
#define CP16(dst, src) asm volatile("cp.async.cg.shared.global [%0], [%1], 16;" \
    :: "r"(dst), "l"(src))
#define CP_COMMIT()   asm volatile("cp.async.commit_group;")

// dyn smem (bf16 elems), 2 stages:
//   Ah[2][64][40]  @ 0      (stage 2560)
//   Al[2][64][40]  @ 5120
//   Bh[2][32][136] @ 10240  (stage 4352)
//   Bl[2][32][136] @ 18944
#define PW_SMEM_ELEMS 27648
#define AH_OFF(s)  ((s)*2560)
#define AL_OFF(s)  (5120  + (s)*2560)
#define BH_OFF(s)  (10240 + (s)*4352)
#define BL_OFF(s)  (18944 + (s)*4352)

__global__ __launch_bounds__(256, 2) void k_pw(
        int wslot, const float* __restrict__ bias,
        const __nv_bfloat16* __restrict__ Xh, const __nv_bfloat16* __restrict__ Xl,
        const float* __restrict__ addsrc, const float* __restrict__ encp,
        float* __restrict__ outf,
        __nv_bfloat16* __restrict__ outh, __nv_bfloat16* __restrict__ outl,
        int mode)
{
    extern __shared__ __nv_bfloat16 smp[];
    const int b  = blockIdx.z;
    const int t0 = blockIdx.x * 128;
    const int o0 = blockIdx.y * 64;
    const size_t bbase = (size_t)b*NCH*LFP;

    const __nv_bfloat16* Wh = g_wh + (size_t)wslot*NCH*NCH;
    const __nv_bfloat16* Wl = g_wl + (size_t)wslot*NCH*NCH;

    const int tid  = threadIdx.x;
    const int lane = tid & 31, warp = tid >> 5;
    const int wm = warp & 1, wn = warp >> 1;

    const int ar = tid >> 2, ac = (tid & 3) << 3;   // A: 64 x 32
    const int br = tid >> 3, bc = (tid & 7) << 4;   // B: 32 x 128, 16 el/thread

    const unsigned smBase = (unsigned)__cvta_generic_to_shared(smp);

    auto prefetch = [&](int s, int kt) {
        int k0 = kt * 32;
        CP16(smBase + (AH_OFF(s) + ar*40 + ac)*2, &Wh[(size_t)(o0 + ar)*NCH + k0 + ac]);
        CP16(smBase + (AL_OFF(s) + ar*40 + ac)*2, &Wl[(size_t)(o0 + ar)*NCH + k0 + ac]);
        size_t xo = bbase + (size_t)(k0 + br)*LFP + t0 + bc;
        CP16(smBase + (BH_OFF(s) + br*136 + bc)*2,     &Xh[xo]);
        CP16(smBase + (BH_OFF(s) + br*136 + bc + 8)*2, &Xh[xo + 8]);
        CP16(smBase + (BL_OFF(s) + br*136 + bc)*2,     &Xl[xo]);
        CP16(smBase + (BL_OFF(s) + br*136 + bc + 8)*2, &Xl[xo + 8]);
    };

    float acc[2][4][4];
    #pragma unroll
    for (int i = 0; i < 2; i++)
        #pragma unroll
        for (int j = 0; j < 4; j++)
            #pragma unroll
            for (int r = 0; r < 4; r++) acc[i][j][r] = 0.f;

    prefetch(0, 0);
    CP_COMMIT();

    #pragma unroll 1
    for (int kt = 0; kt < 8; kt++) {
        const int cur = kt & 1;
        asm volatile("cp.async.wait_group 0;");
        __syncthreads();
        if (kt < 7) {
            prefetch(cur ^ 1, kt + 1);
            CP_COMMIT();
        }

        // Batch ALL ldmatrix for this k-tile (both ks halves) so their latencies
        // overlap each other and the head of the MMA stream.
        unsigned a_hi[2][2][4], a_lo[2][2][4], b_hi[2][2][4], b_lo[2][2][4];
        #pragma unroll
        for (int ks = 0; ks < 2; ks++) {
            const int kb = ks * 16;
            #pragma unroll
            for (int mt = 0; mt < 2; mt++) {
                int rowA = wm*32 + mt*16 + (lane & 15);
                int colA = kb + ((lane >> 4) << 3);
                LDSM4(a_hi[ks][mt], smBase + (AH_OFF(cur) + rowA*40 + colA)*2);
                LDSM4(a_lo[ks][mt], smBase + (AL_OFF(cur) + rowA*40 + colA)*2);
            }
            #pragma unroll
            for (int ng = 0; ng < 2; ng++) {
                int rowB = kb + (lane & 15);
                int colB = wn*32 + ng*16 + ((lane >> 4) << 3);
                LDSM4T(b_hi[ks][ng], smBase + (BH_OFF(cur) + rowB*136 + colB)*2);
                LDSM4T(b_lo[ks][ng], smBase + (BL_OFF(cur) + rowB*136 + colB)*2);
            }
        }
        #pragma unroll
        for (int ks = 0; ks < 2; ks++)
            #pragma unroll
            for (int mt = 0; mt < 2; mt++)
                #pragma unroll
                for (int ng = 0; ng < 2; ng++)
                    #pragma unroll
                    for (int hf = 0; hf < 2; hf++) {
                        int nt = ng*2 + hf;
                        MMA_BF16(acc[mt][nt], a_hi[ks][mt], b_hi[ks][ng][hf*2], b_hi[ks][ng][hf*2+1]);
                        MMA_BF16(acc[mt][nt], a_hi[ks][mt], b_lo[ks][ng][hf*2], b_lo[ks][ng][hf*2+1]);
                        MMA_BF16(acc[mt][nt], a_lo[ks][mt], b_hi[ks][ng][hf*2], b_hi[ks][ng][hf*2+1]);
                    }
    }

    const int g8 = lane >> 2, tq = lane & 3;
    #pragma unroll
    for (int mt = 0; mt < 2; mt++)
        #pragma unroll
        for (int rr = 0; rr < 2; rr++) {
            int o = o0 + wm*32 + mt*16 + rr*8 + g8;
            float bv = bias[o];
            size_t rowo = bbase + (size_t)o*LFP;
            #pragma unroll
            for (int nt = 0; nt < 4; nt++) {
                int t = t0 + wn*32 + nt*8 + tq*2;
                float v0 = acc[mt][nt][rr*2+0] + bv;
                float v1 = acc[mt][nt][rr*2+1] + bv;
                if (mode == 1 || mode == 3) {
                    float2 ad = *(const float2*)&addsrc[rowo + t];
                    v0 += ad.x; v1 += ad.y;
                } else if (mode == 2) {
                    float2 e = *(const float2*)&encp[rowo + t];
                    v0 = fmaxf(v0, 0.f) * e.x;
                    v1 = fmaxf(v1, 0.f) * e.y;
                }
                if (t     >= LF) v0 = 0.f;
                if (t + 1 >= LF) v1 = 0.f;
                if (mode == 3) {
                    __nv_bfloat16 h0, l0, h1, l1;
                    split1(v0, h0, l0); split1(v1, h1, l1);
                    *(__nv_bfloat162*)&outh[rowo + t] = __nv_bfloat162(h0, h1);
                    *(__nv_bfloat162*)&outl[rowo + t] = __nv_bfloat162(l0, l1);
                } else {
                    *(float2*)&outf[rowo + t] = make_float2(v0, v1);
                }
            }
        }
}

// ---------------- fused block chain: prelu -> LN -> 3x(involution + prelu) --------
__global__ __launch_bounds__(256) void k_invchain(
    const float* __restrict__ x,
    const float* __restrict__ lng, const float* __restrict__ lnb,
    const float* __restrict__ alphaScalar,
    const float* __restrict__ prelu_a,
    int bp0,
    __nv_bfloat16* __restrict__ xnh, __nv_bfloat16* __restrict__ xnl,
    float* __restrict__ mout)
{
    __shared__ float w_s[3][3][NCH];
    __shared__ float al_s[3][NCH];
    __shared__ float gs[NCH], bs[NCH];
    __shared__ float lnp[8][2][32];
    __shared__ float part[2][8][3][32];
    __shared__ float bc_s[9];

    const int b    = blockIdx.y;
    const int t0   = blockIdx.x * TILE_INT;
    const int tid  = threadIdx.x;
    const int lane = tid & 31, warp = tid >> 5;
    const int c0   = warp * 32;
    const int tg   = t0 - 3 + lane;
    const bool inseq = (tg >= 0 && tg < LF);
    const bool interior = (lane >= 3 && lane < 3 + TILE_INT) && (tg < LFP);
    const size_t bbase = (size_t)b*NCH*LFP;
    const float aS = *alphaScalar;

    for (int i = tid; i < 9*NCH; i += 256) (&w_s[0][0][0])[i] = g_wc[(size_t)bp0*3*NCH + i];
    for (int i = tid; i < 3*NCH; i += 256) (&al_s[0][0])[i] = prelu_a[i];
    if (tid < NCH) { gs[tid] = lng[tid]; bs[tid] = lnb[tid]; }
    if (tid < 9)   bc_s[tid] = g_bcol[bp0*3 + tid];

    float m[32];
    float s = 0.f, q = 0.f;
    {
        const float* xp = x + bbase + (size_t)c0*LFP + tg;
        #pragma unroll
        for (int i = 0; i < 32; i++) {
            float v = 0.f;
            if (inseq) v = xp[(size_t)i*LFP];
            v = (v >= 0.f) ? v : aS*v;
            m[i] = v; s += v; q += v*v;
        }
    }
    lnp[warp][0][lane] = s; lnp[warp][1][lane] = q;
    __syncthreads();

    float mu, rs;
    {
        float S = 0.f, Q = 0.f;
        #pragma unroll
        for (int w = 0; w < 8; w++) { S += lnp[w][0][lane]; Q += lnp[w][1][lane]; }
        mu = S * (1.f/NCH);
        rs = rsqrtf(Q * (1.f/NCH) - mu*mu + EPSF);
    }

    {
        float p0 = 0.f, p1 = 0.f, p2 = 0.f;
        #pragma unroll
        for (int i = 0; i < 32; i++) {
            int c = c0 + i;
            float v = (m[i] - mu)*rs*gs[c] + bs[c];
            if (!inseq) v = 0.f;
            m[i] = v;
            p0 = fmaf(w_s[0][0][c], v, p0);
            p1 = fmaf(w_s[0][1][c], v, p1);
            p2 = fmaf(w_s[0][2][c], v, p2);
            if (interior) {
                __nv_bfloat16 h, l; split1(v, h, l);
                size_t gi = bbase + (size_t)c*LFP + tg;
                xnh[gi] = h; xnl[gi] = l;
            }
        }
        part[0][warp][0][lane] = p0;
        part[0][warp][1][lane] = p1;
        part[0][warp][2][lane] = p2;
    }
    __syncthreads();

    float k0 = bc_s[0], k1 = bc_s[1], k2 = bc_s[2];
    #pragma unroll
    for (int w = 0; w < 8; w++) {
        k0 += part[0][w][0][lane];
        k1 += part[0][w][1][lane];
        k2 += part[0][w][2][lane];
    }

    #pragma unroll
    for (int st = 0; st < 3; st++) {
        float np0 = 0.f, np1 = 0.f, np2 = 0.f;
        #pragma unroll
        for (int i = 0; i < 32; i++) {
            int c = c0 + i;
            float v  = m[i];
            float vm = __shfl_up_sync(0xffffffffu, v, 1);
            float vp = __shfl_down_sync(0xffffffffu, v, 1);
            float o = k1 * v;
            o = fmaf(k0, vm, o);
            o = fmaf(k2, vp, o);
            float al = al_s[st][c];
            o = (o >= 0.f) ? o : al*o;
            if (!inseq) o = 0.f;
            m[i] = o;
            if (st < 2) {
                np0 = fmaf(w_s[st+1][0][c], o, np0);
                np1 = fmaf(w_s[st+1][1][c], o, np1);
                np2 = fmaf(w_s[st+1][2][c], o, np2);
            } else if (interior) {
                mout[bbase + (size_t)c*LFP + tg] = o;
            }
        }
        if (st < 2) {
            int pb = (st + 1) & 1;
            part[pb][warp][0][lane] = np0;
            part[pb][warp][1][lane] = np1;
            part[pb][warp][2][lane] = np2;
            __syncthreads();
            k0 = bc_s[(st+1)*3 + 0]; k1 = bc_s[(st+1)*3 + 1]; k2 = bc_s[(st+1)*3 + 2];
            #pragma unroll
            for (int w = 0; w < 8; w++) {
                k0 += part[pb][w][0][lane];
                k1 += part[pb][w][1][lane];
                k2 += part[pb][w][2][lane];
            }
        }
    }
}

// ---------------- fused decoder: 16-tap projection + overlap-add ----------------
__global__ __launch_bounds__(256) void k_dec(const float* __restrict__ masked,
                                             const float* __restrict__ dw,
                                             float* __restrict__ outp)
{
    __shared__ float sw[NCH*16];
    __shared__ float hi8[256][8];
    for (int i = threadIdx.x; i < NCH*16; i += 256) sw[i] = dw[i];
    __syncthreads();

    int b = blockIdx.y;
    int f = blockIdx.x*255 + (int)threadIdx.x - 1;
    float acc[16];
    #pragma unroll
    for (int l = 0; l < 16; l++) acc[l] = 0.f;
    if (f >= 0 && f < LF) {
        const float* mb = masked + (size_t)b*NCH*LFP + f;
        #pragma unroll 8
        for (int c = 0; c < NCH; c++) {
            float v = mb[(size_t)c*LFP];
            #pragma unroll
            for (int l = 0; l < 16; l++) acc[l] += v * sw[c*16 + l];
        }
    }
    #pragma unroll
    for (int l = 0; l < 8; l++) hi8[threadIdx.x][l] = acc[8 + l];
    __syncthreads();

    if (threadIdx.x >= 1 && f >= 0 && f < 4096) {
        float* op = outp + (size_t)b*SEQLEN + (size_t)f*8;
        #pragma unroll
        for (int l = 0; l < 8; l++)
            op[l] = acc[l] + hi8[threadIdx.x - 1][l];
    }
}

// ---------------- driver ----------------
extern "C" void kernel_launch(void* const* d_in, const int* in_sizes, int n_in,
                              void* d_out, int out_size)
{
    (void)in_sizes; (void)n_in; (void)out_size;
    const float* noisy_ac    = (const float*)d_in[0];
    const float* noisy_bc    = (const float*)d_in[1];
    const float* ac_w        = (const float*)d_in[2];
    const float* bc_w        = (const float*)d_in[3];
    const float* me_ln_g     = (const float*)d_in[4];
    const float* me_ln_b     = (const float*)d_in[5];
    const float* me_init_w   = (const float*)d_in[6];
    const float* me_init_b   = (const float*)d_in[7];
    const float* blk_ln_g    = (const float*)d_in[8];
    const float* blk_ln_b    = (const float*)d_in[9];
    const float* blk_act_a   = (const float*)d_in[10];
    const float* inv_w1      = (const float*)d_in[11];
    const float* inv_b1      = (const float*)d_in[12];
    const float* inv_w2      = (const float*)d_in[13];
    const float* inv_b2      = (const float*)d_in[14];
    const float* inv_prelu_a = (const float*)d_in[15];
    const float* skip_w      = (const float*)d_in[16];
    const float* skip_b      = (const float*)d_in[17];
    const float* me_final_w  = (const float*)d_in[18];
    const float* me_final_b  = (const float*)d_in[19];
    const float* dec_w       = (const float*)d_in[20];
    float* out = (float*)d_out;

    float *p_enc, *p_x, *p_m1, *p_msk;
    __nv_bfloat16 *p_xnh, *p_xnl, *p_x3h, *p_x3l;
    cudaGetSymbolAddress((void**)&p_enc, g_enc);
    cudaGetSymbolAddress((void**)&p_x,   g_x);
    cudaGetSymbolAddress((void**)&p_m1,  g_m1);
    cudaGetSymbolAddress((void**)&p_msk, g_msk);
    cudaGetSymbolAddress((void**)&p_xnh, g_xnh);
    cudaGetSymbolAddress((void**)&p_xnl, g_xnl);
    cudaGetSymbolAddress((void**)&p_x3h, g_x3h);
    cudaGetSymbolAddress((void**)&p_x3l, g_x3l);

    const int pwSmem = PW_SMEM_ELEMS * (int)sizeof(__nv_bfloat16);   // 55296
    static int attrDone = 0;
    if (!attrDone) {
        cudaFuncSetAttribute(k_pw, cudaFuncAttributeMaxDynamicSharedMemorySize, pwSmem);
        attrDone = 1;
    }

    dim3 pwGrid(32, 4, NB);
    const int invGridX = (LF + TILE_INT - 1) / TILE_INT;

    k_prepsplit<<<dim3(256, 7), 256>>>(inv_w1, inv_b1, inv_w2, inv_b2,
                                       me_init_w, skip_w, me_final_w);
    k_enc_ln<<<dim3(128, NB), dim3(32, 8)>>>(noisy_ac, noisy_bc, ac_w, bc_w,
                                             me_ln_g, me_ln_b, p_enc, p_xnh, p_xnl);
    k_pw<<<pwGrid, 256, pwSmem>>>(0, me_init_b, p_xnh, p_xnl,
                                  nullptr, nullptr, p_x, nullptr, nullptr, 0);

    for (int blk = 0; blk < 4; blk++) {
        k_invchain<<<dim3(invGridX, NB), 256>>>(
            p_x, blk_ln_g + blk*NCH, blk_ln_b + blk*NCH,
            blk_act_a + blk, inv_prelu_a + (size_t)blk*3*NCH, blk*3,
            p_xnh, p_xnl, p_m1);
        if (blk < 3)
            k_pw<<<pwGrid, 256, pwSmem>>>(1 + blk, skip_b + blk*NCH,
                                          p_xnh, p_xnl, p_m1, nullptr,
                                          p_x, nullptr, nullptr, 1);
        else
            k_pw<<<pwGrid, 256, pwSmem>>>(1 + blk, skip_b + blk*NCH,
                                          p_xnh, p_xnl, p_m1, nullptr,
                                          nullptr, p_x3h, p_x3l, 3);
    }

    k_pw<<<pwGrid, 256, pwSmem>>>(5, me_final_b, p_x3h, p_x3l,
                                  nullptr, p_enc, p_msk, nullptr, nullptr, 2);
    k_dec<<<dim3(17, NB), 256>>>(p_msk, dec_w, out);
}

// round 13
// speedup vs baseline: 1.0391x; 1.0391x over previous
#include <cuda_runtime.h>
#include <cuda_bf16.h>
#include <stdint.h>

#define LF     4095
#define LFP    4096
#define NCH    256
#define NB     4
#define SEQLEN 32768
#define EPSF   1e-5f
#define TILE_INT 26

// ---------------- scratch (static device globals; no allocation) ----------------
__device__ float g_enc [NB*NCH*LFP];
__device__ float g_x   [NB*NCH*LFP];
__device__ float g_m1  [NB*NCH*LFP];
__device__ float g_msk [NB*NCH*LFP];
__device__ __nv_bfloat16 g_xnh[NB*NCH*LFP];
__device__ __nv_bfloat16 g_xnl[NB*NCH*LFP];
__device__ __nv_bfloat16 g_x3h[NB*NCH*LFP];
__device__ __nv_bfloat16 g_x3l[NB*NCH*LFP];
__device__ float g_wc  [12*3*NCH];
__device__ float g_bcol[12*3];
__device__ __nv_bfloat16 g_wh[6*NCH*NCH];
__device__ __nv_bfloat16 g_wl[6*NCH*NCH];

__device__ __forceinline__ void split1(float x, __nv_bfloat16& h, __nv_bfloat16& l)
{
    h = __float2bfloat16(x);
    l = __float2bfloat16(x - __bfloat162float(h));
}

// ---------------- collapse w2@w1 (+ bias) ----------------
__global__ void k_prep(const float* __restrict__ w1, const float* __restrict__ b1,
                       const float* __restrict__ w2, const float* __restrict__ b2)
{
    int bp = blockIdx.x, j = blockIdx.y, c = threadIdx.x;
    const float* w1p = w1 + (size_t)bp*64*NCH;
    const float* w2p = w2 + ((size_t)bp*3 + j)*64;
    float acc = 0.f;
    #pragma unroll 8
    for (int cr = 0; cr < 64; cr++) acc += w2p[cr] * w1p[(size_t)cr*NCH + c];
    g_wc[((size_t)bp*3 + j)*NCH + c] = acc;
    if (c == 0) {
        const float* b1p = b1 + bp*64;
        float bb = b2[bp*3 + j];
        for (int cr = 0; cr < 64; cr++) bb += w2p[cr]*b1p[cr];
        g_bcol[bp*3 + j] = bb;
    }
}

// ---------------- split 6 weight matrices into bf16 hi/lo ----------------
__global__ void k_wsplit(const float* __restrict__ mi, const float* __restrict__ sk,
                         const float* __restrict__ mf)
{
    int slot = blockIdx.y;
    int idx  = blockIdx.x*256 + threadIdx.x;
    const float* src = (slot == 0) ? mi : (slot <= 4 ? sk + (size_t)(slot-1)*NCH*NCH : mf);
    float v = src[idx];
    __nv_bfloat16 h, l; split1(v, h, l);
    g_wh[(size_t)slot*NCH*NCH + idx] = h;
    g_wl[(size_t)slot*NCH*NCH + idx] = l;
}

// ---------------- encoder + fused channel-LN ----------------
__global__ void k_enc_ln(const float* __restrict__ ac, const float* __restrict__ bc,
                         const float* __restrict__ acw, const float* __restrict__ bcw,
                         const float* __restrict__ lng, const float* __restrict__ lnb,
                         float* __restrict__ enc,
                         __nv_bfloat16* __restrict__ xnh, __nv_bfloat16* __restrict__ xnl)
{
    int b  = blockIdx.y;
    int t0 = blockIdx.x * 32;
    int tx = threadIdx.x, ty = threadIdx.y;
    __shared__ float sa[264], sb[264];
    __shared__ float ss[8][33], sq[8][33];
    int tid  = ty*32 + tx;
    int base = t0 * 8;
    for (int i = tid; i < 264; i += 256) {
        int gi = base + i;
        sa[i] = (gi < SEQLEN) ? ac[(size_t)b*SEQLEN + gi] : 0.f;
        sb[i] = (gi < SEQLEN) ? bc[(size_t)b*SEQLEN + gi] : 0.f;
    }
    __syncthreads();
    int t = t0 + tx;
    bool valid = (t < LF);
    const size_t bbase = (size_t)b*NCH*LFP;
    float vals[32];
    float s = 0.f, q = 0.f;
    #pragma unroll
    for (int i = 0; i < 32; i++) {
        int n = ty + i*8;
        float acc = 0.f;
        #pragma unroll
        for (int l = 0; l < 16; l++)
            acc += sa[tx*8 + l]*acw[n*16 + l] + sb[tx*8 + l]*bcw[n*16 + l];
        if (!valid) acc = 0.f;
        vals[i] = acc; s += acc; q += acc*acc;
        enc[bbase + (size_t)n*LFP + t] = acc;
    }
    ss[ty][tx] = s; sq[ty][tx] = q;
    __syncthreads();
    if (ty == 0) {
        float S = 0.f, Q = 0.f;
        #pragma unroll
        for (int j = 0; j < 8; j++) { S += ss[j][tx]; Q += sq[j][tx]; }
        float mu  = S * (1.f/NCH);
        float var = Q * (1.f/NCH) - mu*mu;
        ss[0][tx] = mu;
        sq[0][tx] = rsqrtf(var + EPSF);
    }
    __syncthreads();
    float mu = ss[0][tx], rs = sq[0][tx];
    #pragma unroll
    for (int i = 0; i < 32; i++) {
        int c = ty + i*8;
        float v = valid ? (vals[i] - mu)*rs*lng[c] + lnb[c] : 0.f;
        __nv_bfloat16 h, l; split1(v, h, l);
        size_t gi = bbase + (size_t)c*LFP + t;
        xnh[gi] = h; xnl[gi] = l;
    }
}

// ---------------- tensor-core pointwise GEMM: A-resident + pair-local B pipeline --
#define LDSM4(R, addr)  asm volatile("ldmatrix.sync.aligned.m8n8.x4.shared.b16 {%0,%1,%2,%3}, [%4];" \
    : "=r"(R[0]),"=r"(R[1]),"=r"(R[2]),"=r"(R[3]) : "r"(addr))
#define LDSM4T(R, addr) asm volatile("ldmatrix.sync.aligned.m8n8.x4.trans.shared.b16 {%0,%1,%2,%3}, [%4];" \
    : "=r"(R[0]),"=r"(R[1]),"=r"(R[2]),"=r"(R[3]) : "r"(addr))
#define MMA_BF16(D, A, B0, B1) asm volatile( \
    "mma.sync.aligned.m16n8k16.row.col.f32.bf16.bf16.f32 " \
    "{%0,%1,%2,%3}, {%4,%5,%6,%7}, {%8,%9}, {%0,%1,%2,%3};" \
    : "+f"(D[0]), "+f"(D[1]), "+f"(D[2]), "+f"(D[3]) \
    : "r"(A[0]), "r"(A[1]), "r"(A[2]), "r"(A[3]), "r"(B0), "r"(B1))
#define CP16(dst, src) asm volatile("cp.async.cg.shared.global [%0], [%1], 16;" \
    :: "r"(dst), "l"(src))
#define CP_COMMIT()   asm volatile("cp.async.commit_group;")

// smem element map (bf16):
//   Ah[64][264] @ 0        (o 64 x K 256, pitch 264)
//   Al[64][264] @ 16896
//   B stages:   @ 33792 : pair p, stage s, hl -> 1280 el each ([32k][40t])
#define APITCH    264
#define A_H_OFF   0
#define A_L_OFF   16896
#define B_OFF     33792
#define BSTG(p, s, hl) (B_OFF + ((((p)*2 + (s))*2 + (hl))*1280))
#define PW_SMEM_ELEMS 54272   // 108544 bytes -> 2 CTAs/SM

__global__ __launch_bounds__(256, 2) void k_pw(
        int wslot, const float* __restrict__ bias,
        const __nv_bfloat16* __restrict__ Xh, const __nv_bfloat16* __restrict__ Xl,
        const float* __restrict__ addsrc, const float* __restrict__ encp,
        float* __restrict__ outf,
        __nv_bfloat16* __restrict__ outh, __nv_bfloat16* __restrict__ outl,
        int mode)
{
    extern __shared__ __nv_bfloat16 smp[];
    const int b  = blockIdx.z;
    const int t0 = blockIdx.x * 128;
    const int o0 = blockIdx.y * 64;
    const size_t bbase = (size_t)b*NCH*LFP;

    const __nv_bfloat16* Wh = g_wh + (size_t)wslot*NCH*NCH;
    const __nv_bfloat16* Wl = g_wl + (size_t)wslot*NCH*NCH;

    const int tid  = threadIdx.x;
    const int lane = tid & 31, warp = tid >> 5;
    const int wm = warp & 1, wn = warp >> 1;
    const int pair = wn;                 // warps {2p,2p+1} own t-range p*32..+32
    const int barid = pair + 1;          // named barriers 1..4

    const unsigned smBase = (unsigned)__cvta_generic_to_shared(smp);

    // ---- A cooperative resident load ----
    #pragma unroll
    for (int it = 0; it < 8; it++) {
        int g = it*256 + tid;
        int row = g >> 5, k8 = (g & 31) << 3;
        CP16(smBase + (unsigned)(A_H_OFF + row*APITCH + k8)*2, &Wh[(size_t)(o0 + row)*NCH + k8]);
        CP16(smBase + (unsigned)(A_L_OFF + row*APITCH + k8)*2, &Wl[(size_t)(o0 + row)*NCH + k8]);
    }
    CP_COMMIT();                         // group A

    // ---- pair-local B chunk loader ----
    auto loadB = [&](int s, int kt) {
        int lt = tid & 63;
        #pragma unroll
        for (int it = 0; it < 2; it++) {
            int g = it*64 + lt;
            int row = g >> 2, t8 = (g & 3) << 3;
            size_t xo = bbase + (size_t)(kt*32 + row)*LFP + t0 + pair*32 + t8;
            CP16(smBase + (unsigned)(BSTG(pair, s, 0) + row*40 + t8)*2, &Xh[xo]);
            CP16(smBase + (unsigned)(BSTG(pair, s, 1) + row*40 + t8)*2, &Xl[xo]);
        }
    };
    loadB(0, 0); CP_COMMIT();            // group B0
    loadB(1, 1); CP_COMMIT();            // group B1

    asm volatile("cp.async.wait_group 2;");   // A arrived
    __syncthreads();                          // A visible CTA-wide (only CTA barrier)

    float acc[2][4][4];
    #pragma unroll
    for (int i = 0; i < 2; i++)
        #pragma unroll
        for (int j = 0; j < 4; j++)
            #pragma unroll
            for (int r = 0; r < 4; r++) acc[i][j][r] = 0.f;

    #pragma unroll 1
    for (int kt = 0; kt < 8; kt++) {
        const int s = kt & 1;
        // B_kt complete: for kt<7 one newer group may remain in flight; at kt=7
        // B7 IS the last group, so drain fully (this was the R12 corruption bug).
        if (kt < 7) asm volatile("cp.async.wait_group 1;");
        else        asm volatile("cp.async.wait_group 0;");
        asm volatile("bar.sync %0, 64;" :: "r"(barid));    // partner's B_kt visible

        unsigned a_hi[2][2][4], a_lo[2][2][4], b_hi[2][2][4], b_lo[2][2][4];
        #pragma unroll
        for (int ks = 0; ks < 2; ks++) {
            const int kb = ks * 16;
            #pragma unroll
            for (int mt = 0; mt < 2; mt++) {
                int rowA = wm*32 + mt*16 + (lane & 15);
                int colA = kt*32 + kb + ((lane >> 4) << 3);
                LDSM4(a_hi[ks][mt], smBase + (unsigned)(A_H_OFF + rowA*APITCH + colA)*2);
                LDSM4(a_lo[ks][mt], smBase + (unsigned)(A_L_OFF + rowA*APITCH + colA)*2);
            }
            #pragma unroll
            for (int ng = 0; ng < 2; ng++) {
                int rowB = kb + (lane & 15);
                int colB = ng*16 + ((lane >> 4) << 3);
                LDSM4T(b_hi[ks][ng], smBase + (unsigned)(BSTG(pair, s, 0) + rowB*40 + colB)*2);
                LDSM4T(b_lo[ks][ng], smBase + (unsigned)(BSTG(pair, s, 1) + rowB*40 + colB)*2);
            }
        }
        #pragma unroll
        for (int ks = 0; ks < 2; ks++)
            #pragma unroll
            for (int mt = 0; mt < 2; mt++)
                #pragma unroll
                for (int ng = 0; ng < 2; ng++)
                    #pragma unroll
                    for (int hf = 0; hf < 2; hf++) {
                        int nt = ng*2 + hf;
                        MMA_BF16(acc[mt][nt], a_hi[ks][mt], b_hi[ks][ng][hf*2], b_hi[ks][ng][hf*2+1]);
                        MMA_BF16(acc[mt][nt], a_hi[ks][mt], b_lo[ks][ng][hf*2], b_lo[ks][ng][hf*2+1]);
                        MMA_BF16(acc[mt][nt], a_lo[ks][mt], b_hi[ks][ng][hf*2], b_hi[ks][ng][hf*2+1]);
                    }

        asm volatile("bar.sync %0, 64;" :: "r"(barid));    // partner done reading stage s
        if (kt < 6) { loadB(s, kt + 2); CP_COMMIT(); }
    }

    const int g8 = lane >> 2, tq = lane & 3;
    #pragma unroll
    for (int mt = 0; mt < 2; mt++)
        #pragma unroll
        for (int rr = 0; rr < 2; rr++) {
            int o = o0 + wm*32 + mt*16 + rr*8 + g8;
            float bv = bias[o];
            size_t rowo = bbase + (size_t)o*LFP;
            #pragma unroll
            for (int nt = 0; nt < 4; nt++) {
                int t = t0 + wn*32 + nt*8 + tq*2;
                float v0 = acc[mt][nt][rr*2+0] + bv;
                float v1 = acc[mt][nt][rr*2+1] + bv;
                if (mode == 1 || mode == 3) {
                    float2 ad = *(const float2*)&addsrc[rowo + t];
                    v0 += ad.x; v1 += ad.y;
                } else if (mode == 2) {
                    float2 e = *(const float2*)&encp[rowo + t];
                    v0 = fmaxf(v0, 0.f) * e.x;
                    v1 = fmaxf(v1, 0.f) * e.y;
                }
                if (t     >= LF) v0 = 0.f;
                if (t + 1 >= LF) v1 = 0.f;
                if (mode == 3) {
                    __nv_bfloat16 h0, l0, h1, l1;
                    split1(v0, h0, l0); split1(v1, h1, l1);
                    *(__nv_bfloat162*)&outh[rowo + t] = __nv_bfloat162(h0, h1);
                    *(__nv_bfloat162*)&outl[rowo + t] = __nv_bfloat162(l0, l1);
                } else {
                    *(float2*)&outf[rowo + t] = make_float2(v0, v1);
                }
            }
        }
}

// ---------------- fused block chain: prelu -> LN -> 3x(involution + prelu) --------
__global__ __launch_bounds__(256) void k_invchain(
    const float* __restrict__ x,
    const float* __restrict__ lng, const float* __restrict__ lnb,
    const float* __restrict__ alphaScalar,
    const float* __restrict__ prelu_a,
    int bp0,
    __nv_bfloat16* __restrict__ xnh, __nv_bfloat16* __restrict__ xnl,
    float* __restrict__ mout)
{
    __shared__ float w_s[3][3][NCH];
    __shared__ float al_s[3][NCH];
    __shared__ float gs[NCH], bs[NCH];
    __shared__ float lnp[8][2][32];
    __shared__ float part[2][8][3][32];
    __shared__ float bc_s[9];

    const int b    = blockIdx.y;
    const int t0   = blockIdx.x * TILE_INT;
    const int tid  = threadIdx.x;
    const int lane = tid & 31, warp = tid >> 5;
    const int c0   = warp * 32;
    const int tg   = t0 - 3 + lane;
    const bool inseq = (tg >= 0 && tg < LF);
    const bool interior = (lane >= 3 && lane < 3 + TILE_INT) && (tg < LFP);
    const size_t bbase = (size_t)b*NCH*LFP;
    const float aS = *alphaScalar;

    for (int i = tid; i < 9*NCH; i += 256) (&w_s[0][0][0])[i] = g_wc[(size_t)bp0*3*NCH + i];
    for (int i = tid; i < 3*NCH; i += 256) (&al_s[0][0])[i] = prelu_a[i];
    if (tid < NCH) { gs[tid] = lng[tid]; bs[tid] = lnb[tid]; }
    if (tid < 9)   bc_s[tid] = g_bcol[bp0*3 + tid];

    float m[32];
    float s = 0.f, q = 0.f;
    {
        const float* xp = x + bbase + (size_t)c0*LFP + tg;
        #pragma unroll
        for (int i = 0; i < 32; i++) {
            float v = 0.f;
            if (inseq) v = xp[(size_t)i*LFP];
            v = (v >= 0.f) ? v : aS*v;
            m[i] = v; s += v; q += v*v;
        }
    }
    lnp[warp][0][lane] = s; lnp[warp][1][lane] = q;
    __syncthreads();

    float mu, rs;
    {
        float S = 0.f, Q = 0.f;
        #pragma unroll
        for (int w = 0; w < 8; w++) { S += lnp[w][0][lane]; Q += lnp[w][1][lane]; }
        mu = S * (1.f/NCH);
        rs = rsqrtf(Q * (1.f/NCH) - mu*mu + EPSF);
    }

    {
        float p0 = 0.f, p1 = 0.f, p2 = 0.f;
        #pragma unroll
        for (int i = 0; i < 32; i++) {
            int c = c0 + i;
            float v = (m[i] - mu)*rs*gs[c] + bs[c];
            if (!inseq) v = 0.f;
            m[i] = v;
            p0 = fmaf(w_s[0][0][c], v, p0);
            p1 = fmaf(w_s[0][1][c], v, p1);
            p2 = fmaf(w_s[0][2][c], v, p2);
            if (interior) {
                __nv_bfloat16 h, l; split1(v, h, l);
                size_t gi = bbase + (size_t)c*LFP + tg;
                xnh[gi] = h; xnl[gi] = l;
            }
        }
        part[0][warp][0][lane] = p0;
        part[0][warp][1][lane] = p1;
        part[0][warp][2][lane] = p2;
    }
    __syncthreads();

    float k0 = bc_s[0], k1 = bc_s[1], k2 = bc_s[2];
    #pragma unroll
    for (int w = 0; w < 8; w++) {
        k0 += part[0][w][0][lane];
        k1 += part[0][w][1][lane];
        k2 += part[0][w][2][lane];
    }

    #pragma unroll
    for (int st = 0; st < 3; st++) {
        float np0 = 0.f, np1 = 0.f, np2 = 0.f;
        #pragma unroll
        for (int i = 0; i < 32; i++) {
            int c = c0 + i;
            float v  = m[i];
            float vm = __shfl_up_sync(0xffffffffu, v, 1);
            float vp = __shfl_down_sync(0xffffffffu, v, 1);
            float o = k1 * v;
            o = fmaf(k0, vm, o);
            o = fmaf(k2, vp, o);
            float al = al_s[st][c];
            o = (o >= 0.f) ? o : al*o;
            if (!inseq) o = 0.f;
            m[i] = o;
            if (st < 2) {
                np0 = fmaf(w_s[st+1][0][c], o, np0);
                np1 = fmaf(w_s[st+1][1][c], o, np1);
                np2 = fmaf(w_s[st+1][2][c], o, np2);
            } else if (interior) {
                mout[bbase + (size_t)c*LFP + tg] = o;
            }
        }
        if (st < 2) {
            int pb = (st + 1) & 1;
            part[pb][warp][0][lane] = np0;
            part[pb][warp][1][lane] = np1;
            part[pb][warp][2][lane] = np2;
            __syncthreads();
            k0 = bc_s[(st+1)*3 + 0]; k1 = bc_s[(st+1)*3 + 1]; k2 = bc_s[(st+1)*3 + 2];
            #pragma unroll
            for (int w = 0; w < 8; w++) {
                k0 += part[pb][w][0][lane];
                k1 += part[pb][w][1][lane];
                k2 += part[pb][w][2][lane];
            }
        }
    }
}

// ---------------- fused decoder: 16-tap projection + overlap-add ----------------
__global__ __launch_bounds__(256) void k_dec(const float* __restrict__ masked,
                                             const float* __restrict__ dw,
                                             float* __restrict__ outp)
{
    __shared__ float sw[NCH*16];
    __shared__ float hi8[256][8];
    for (int i = threadIdx.x; i < NCH*16; i += 256) sw[i] = dw[i];
    __syncthreads();

    int b = blockIdx.y;
    int f = blockIdx.x*255 + (int)threadIdx.x - 1;
    float acc[16];
    #pragma unroll
    for (int l = 0; l < 16; l++) acc[l] = 0.f;
    if (f >= 0 && f < LF) {
        const float* mb = masked + (size_t)b*NCH*LFP + f;
        #pragma unroll 8
        for (int c = 0; c < NCH; c++) {
            float v = mb[(size_t)c*LFP];
            #pragma unroll
            for (int l = 0; l < 16; l++) acc[l] += v * sw[c*16 + l];
        }
    }
    #pragma unroll
    for (int l = 0; l < 8; l++) hi8[threadIdx.x][l] = acc[8 + l];
    __syncthreads();

    if (threadIdx.x >= 1 && f >= 0 && f < 4096) {
        float* op = outp + (size_t)b*SEQLEN + (size_t)f*8;
        #pragma unroll
        for (int l = 0; l < 8; l++)
            op[l] = acc[l] + hi8[threadIdx.x - 1][l];
    }
}

// ---------------- driver ----------------
extern "C" void kernel_launch(void* const* d_in, const int* in_sizes, int n_in,
                              void* d_out, int out_size)
{
    (void)in_sizes; (void)n_in; (void)out_size;
    const float* noisy_ac    = (const float*)d_in[0];
    const float* noisy_bc    = (const float*)d_in[1];
    const float* ac_w        = (const float*)d_in[2];
    const float* bc_w        = (const float*)d_in[3];
    const float* me_ln_g     = (const float*)d_in[4];
    const float* me_ln_b     = (const float*)d_in[5];
    const float* me_init_w   = (const float*)d_in[6];
    const float* me_init_b   = (const float*)d_in[7];
    const float* blk_ln_g    = (const float*)d_in[8];
    const float* blk_ln_b    = (const float*)d_in[9];
    const float* blk_act_a   = (const float*)d_in[10];
    const float* inv_w1      = (const float*)d_in[11];
    const float* inv_b1      = (const float*)d_in[12];
    const float* inv_w2      = (const float*)d_in[13];
    const float* inv_b2      = (const float*)d_in[14];
    const float* inv_prelu_a = (const float*)d_in[15];
    const float* skip_w      = (const float*)d_in[16];
    const float* skip_b      = (const float*)d_in[17];
    const float* me_final_w  = (const float*)d_in[18];
    const float* me_final_b  = (const float*)d_in[19];
    const float* dec_w       = (const float*)d_in[20];
    float* out = (float*)d_out;

    float *p_enc, *p_x, *p_m1, *p_msk;
    __nv_bfloat16 *p_xnh, *p_xnl, *p_x3h, *p_x3l;
    cudaGetSymbolAddress((void**)&p_enc, g_enc);
    cudaGetSymbolAddress((void**)&p_x,   g_x);
    cudaGetSymbolAddress((void**)&p_m1,  g_m1);
    cudaGetSymbolAddress((void**)&p_msk, g_msk);
    cudaGetSymbolAddress((void**)&p_xnh, g_xnh);
    cudaGetSymbolAddress((void**)&p_xnl, g_xnl);
    cudaGetSymbolAddress((void**)&p_x3h, g_x3h);
    cudaGetSymbolAddress((void**)&p_x3l, g_x3l);

    const int pwSmem = PW_SMEM_ELEMS * (int)sizeof(__nv_bfloat16);   // 108544
    static int attrDone = 0;
    if (!attrDone) {
        cudaFuncSetAttribute(k_pw, cudaFuncAttributeMaxDynamicSharedMemorySize, pwSmem);
        attrDone = 1;
    }

    dim3 pwGrid(32, 4, NB);
    const int invGridX = (LF + TILE_INT - 1) / TILE_INT;

    k_prep  <<<dim3(12, 3), 256>>>(inv_w1, inv_b1, inv_w2, inv_b2);
    k_wsplit<<<dim3(256, 6), 256>>>(me_init_w, skip_w, me_final_w);
    k_enc_ln<<<dim3(128, NB), dim3(32, 8)>>>(noisy_ac, noisy_bc, ac_w, bc_w,
                                             me_ln_g, me_ln_b, p_enc, p_xnh, p_xnl);
    k_pw<<<pwGrid, 256, pwSmem>>>(0, me_init_b, p_xnh, p_xnl,
                                  nullptr, nullptr, p_x, nullptr, nullptr, 0);

    for (int blk = 0; blk < 4; blk++) {
        k_invchain<<<dim3(invGridX, NB), 256>>>(
            p_x, blk_ln_g + blk*NCH, blk_ln_b + blk*NCH,
            blk_act_a + blk, inv_prelu_a + (size_t)blk*3*NCH, blk*3,
            p_xnh, p_xnl, p_m1);
        if (blk < 3)
            k_pw<<<pwGrid, 256, pwSmem>>>(1 + blk, skip_b + blk*NCH,
                                          p_xnh, p_xnl, p_m1, nullptr,
                                          p_x, nullptr, nullptr, 1);
        else
            k_pw<<<pwGrid, 256, pwSmem>>>(1 + blk, skip_b + blk*NCH,
                                          p_xnh, p_xnl, p_m1, nullptr,
                                          nullptr, p_x3h, p_x3l, 3);
    }

    k_pw<<<pwGrid, 256, pwSmem>>>(5, me_final_b, p_x3h, p_x3l,
                                  nullptr, p_enc, p_msk, nullptr, nullptr, 2);
    k_dec<<<dim3(17, NB), 256>>>(p_msk, dec_w, out);
}